// round 2
// baseline (speedup 1.0000x reference)
#include <cuda_runtime.h>
#include <cuda_fp16.h>
#include <cstdint>

// Problem constants
#define BB 4
#define TT 32
#define NN 32
#define FF 16
#define GH 64
#define LSTM_IN 2048     // NN*GH
#define LSTM_H 4096
#define GATES 16384      // 4*LSTM_H
#define E_EDGES 256

// Scratch (device globals; no dynamic allocation allowed)
__device__ float g_A[NN * NN];
__device__ float g_seq[BB * TT * LSTM_IN];            // 1 MB
__device__ float g_xproj[TT * BB * GATES];            // 8 MB
__device__ float g_h2[2][BB * LSTM_H];                // double-buffered hidden
__device__ float g_c[BB * LSTM_H];
__device__ __half g_Whh_h[(size_t)GATES * LSTM_H];    // 128 MiB fp16 weights

// ---------- packed f32x2 helpers (sm_103a FFMA2 path, used in xproj) ----------
__device__ __forceinline__ unsigned long long pack2(float lo, float hi) {
    unsigned long long r;
    unsigned int l = __float_as_uint(lo), h = __float_as_uint(hi);
    asm("mov.b64 %0, {%1, %2};" : "=l"(r) : "r"(l), "r"(h));
    return r;
}
__device__ __forceinline__ void ffma2(unsigned long long& d,
                                      unsigned long long a,
                                      unsigned long long b) {
    asm("fma.rn.f32x2 %0, %1, %2, %0;" : "+l"(d) : "l"(a), "l"(b));
}
__device__ __forceinline__ float2 unpack2(unsigned long long v) {
    unsigned int l, h;
    asm("mov.b64 {%0, %1}, %2;" : "=r"(l), "=r"(h) : "l"(v));
    float2 r;
    r.x = __uint_as_float(l);
    r.y = __uint_as_float(h);
    return r;
}

// ---------- 1) adjacency build (handles int32 or int64 edge_index) ----------
__global__ void build_adj_kernel(const int* __restrict__ ei32) {
    __shared__ int is32flag;
    __shared__ int deg[NN];
    __shared__ float dinv[NN];
    __shared__ float As[NN * NN];
    int tid = threadIdx.x;
    if (tid == 0) is32flag = 0;
    for (int i = tid; i < NN; i += blockDim.x) deg[i] = 1;  // self loop
    for (int i = tid; i < NN * NN; i += blockDim.x) As[i] = 0.f;
    __syncthreads();
    // If stored as int64 (values < 32), every odd 32-bit word (high half) is 0.
    int any = 0;
    for (int w = tid * 2 + 1; w < 512; w += blockDim.x * 2) any |= ei32[w];
    if (any) atomicOr(&is32flag, 1);
    __syncthreads();
    const int is32 = is32flag;
    for (int e = tid; e < E_EDGES; e += blockDim.x) {
        int dst = is32 ? ei32[E_EDGES + e] : ei32[2 * (E_EDGES + e)];
        atomicAdd(&deg[dst], 1);
    }
    __syncthreads();
    for (int i = tid; i < NN; i += blockDim.x) dinv[i] = rsqrtf((float)deg[i]);
    __syncthreads();
    for (int e = tid; e < E_EDGES; e += blockDim.x) {
        int src = is32 ? ei32[e] : ei32[2 * e];
        int dst = is32 ? ei32[E_EDGES + e] : ei32[2 * (E_EDGES + e)];
        atomicAdd(&As[dst * NN + src], dinv[src] * dinv[dst]);
    }
    for (int n = tid; n < NN; n += blockDim.x)
        atomicAdd(&As[n * NN + n], dinv[n] * dinv[n]);
    __syncthreads();
    for (int i = tid; i < NN * NN; i += blockDim.x) g_A[i] = As[i];
}

// ---------- 2) LayerNorm + GCN x2 -> seq[bt][n*GH+g] ----------
__global__ void __launch_bounds__(256) gcn_kernel(
    const float* __restrict__ x, const float* __restrict__ ln_g,
    const float* __restrict__ ln_b, const float* __restrict__ W1,
    const float* __restrict__ b1, const float* __restrict__ W2,
    const float* __restrict__ b2) {
    __shared__ float xln[NN * FF];
    __shared__ float bufA[NN * GH];
    __shared__ float bufB[NN * GH];
    __shared__ float As[NN * NN];
    int tid = threadIdx.x;
    int bt = blockIdx.x;  // b*TT + t
    const float* xp = x + (size_t)bt * NN * FF;

    for (int i = tid; i < NN * NN; i += 256) As[i] = g_A[i];
    if (tid < NN) {
        float v[FF];
        float mu = 0.f;
#pragma unroll
        for (int f = 0; f < FF; f++) { v[f] = xp[tid * FF + f]; mu += v[f]; }
        mu *= (1.f / FF);
        float var = 0.f;
#pragma unroll
        for (int f = 0; f < FF; f++) { float d = v[f] - mu; var += d * d; }
        var *= (1.f / FF);
        float r = rsqrtf(var + 1e-5f);
#pragma unroll
        for (int f = 0; f < FF; f++)
            xln[tid * FF + f] = (v[f] - mu) * r * ln_g[f] + ln_b[f];
    }
    __syncthreads();
    // t1 = xln @ W1
    for (int o = tid; o < NN * GH; o += 256) {
        int n = o >> 6, g = o & 63;
        float s = 0.f;
#pragma unroll
        for (int f = 0; f < FF; f++) s += xln[n * FF + f] * W1[f * GH + g];
        bufA[o] = s;
    }
    __syncthreads();
    // agg1 = A @ t1 + b1
    for (int o = tid; o < NN * GH; o += 256) {
        int n = o >> 6, g = o & 63;
        float s = b1[g];
#pragma unroll 8
        for (int sn = 0; sn < NN; sn++) s += As[n * NN + sn] * bufA[sn * GH + g];
        bufB[o] = s;
    }
    __syncthreads();
    // t2 = agg1 @ W2
    for (int o = tid; o < NN * GH; o += 256) {
        int n = o >> 6, g = o & 63;
        float s = 0.f;
#pragma unroll 8
        for (int f = 0; f < GH; f++) s += bufB[n * GH + f] * W2[f * GH + g];
        bufA[o] = s;
    }
    __syncthreads();
    // out = A @ t2 + b2 -> seq
    for (int o = tid; o < NN * GH; o += 256) {
        int n = o >> 6, g = o & 63;
        float s = b2[g];
#pragma unroll 8
        for (int sn = 0; sn < NN; sn++) s += As[n * NN + sn] * bufA[sn * GH + g];
        g_seq[(size_t)bt * LSTM_IN + o] = s;
    }
}

// ---------- 3) x_proj = seq @ W_ih^T + (b_ih + b_hh) ----------
// M=128 (bt), N=16384 (gates), K=2048. Tile 128x128 per block, grid 128.
__global__ void __launch_bounds__(256) xproj_gemm_kernel(
    const float* __restrict__ Wih, const float* __restrict__ b_ih,
    const float* __restrict__ b_hh) {
    __shared__ float Ss[16][128];
    __shared__ float Ws[16][128];
    int tid = threadIdx.x;
    int tx = tid & 15, ty = tid >> 4;
    int gbase = blockIdx.x * 128;
    unsigned long long acc[8][4];
#pragma unroll
    for (int i = 0; i < 8; i++)
#pragma unroll
        for (int p = 0; p < 4; p++) acc[i][p] = 0ull;

    for (int kc = 0; kc < 2048; kc += 16) {
#pragma unroll
        for (int i = 0; i < 2; i++) {
            int idx = tid + i * 256;  // 512 float4 tiles
            int row = idx >> 2, c = idx & 3;
            float4 v = *(const float4*)&g_seq[(size_t)row * 2048 + kc + c * 4];
            Ss[c * 4 + 0][row] = v.x;
            Ss[c * 4 + 1][row] = v.y;
            Ss[c * 4 + 2][row] = v.z;
            Ss[c * 4 + 3][row] = v.w;
            float4 w = *(const float4*)(Wih + (size_t)(gbase + row) * 2048 + kc + c * 4);
            Ws[c * 4 + 0][row] = w.x;
            Ws[c * 4 + 1][row] = w.y;
            Ws[c * 4 + 2][row] = w.z;
            Ws[c * 4 + 3][row] = w.w;
        }
        __syncthreads();
#pragma unroll
        for (int kk = 0; kk < 16; kk++) {
            float4 a0 = *(float4*)&Ss[kk][ty * 8];
            float4 a1 = *(float4*)&Ss[kk][ty * 8 + 4];
            float4 b0 = *(float4*)&Ws[kk][tx * 8];
            float4 b1 = *(float4*)&Ws[kk][tx * 8 + 4];
            unsigned long long bp[4] = {pack2(b0.x, b0.y), pack2(b0.z, b0.w),
                                        pack2(b1.x, b1.y), pack2(b1.z, b1.w)};
            float av[8] = {a0.x, a0.y, a0.z, a0.w, a1.x, a1.y, a1.z, a1.w};
#pragma unroll
            for (int i = 0; i < 8; i++) {
                unsigned long long ap = pack2(av[i], av[i]);
                ffma2(acc[i][0], ap, bp[0]);
                ffma2(acc[i][1], ap, bp[1]);
                ffma2(acc[i][2], ap, bp[2]);
                ffma2(acc[i][3], ap, bp[3]);
            }
        }
        __syncthreads();
    }
#pragma unroll
    for (int i = 0; i < 8; i++) {
        int m = ty * 8 + i;
        int t = m & 31, b = m >> 5;
        float* outp = g_xproj + (size_t)t * BB * GATES + (size_t)b * GATES + gbase + tx * 8;
#pragma unroll
        for (int p = 0; p < 4; p++) {
            float2 v = unpack2(acc[i][p]);
            int g = gbase + tx * 8 + 2 * p;
            outp[2 * p] = v.x + b_ih[g] + b_hh[g];
            outp[2 * p + 1] = v.y + b_ih[g + 1] + b_hh[g + 1];
        }
    }
}

// ---------- 4) convert W_hh -> fp16 (once per launch; halves step traffic) ----
__global__ void __launch_bounds__(256) convert_whh_kernel(const float* __restrict__ Whh) {
    size_t i = ((size_t)blockIdx.x * 256 + threadIdx.x) * 4;  // 4 elems/thread
    float4 v = *(const float4*)(Whh + i);
    __half2* out = (__half2*)(g_Whh_h + i);
    out[0] = __floats2half2_rn(v.x, v.y);
    out[1] = __floats2half2_rn(v.z, v.w);
}

// ---------- 5) init h,c ----------
__global__ void init_hc_kernel() {
    int idx = blockIdx.x * 256 + threadIdx.x;  // < 32768
    if (idx < BB * LSTM_H) g_h2[0][idx] = 0.f;
    else g_c[idx - BB * LSTM_H] = 0.f;
}

// ---------- 6) fused LSTM step: gates GEMV (fp16 W, fp32 acc) + cell update ----
// Warp handles 4 hidden indices x 4 gate types x 4 batches = 64 dot products.
// Block = 8 warps = 32 hidden indices; grid = 4096/32 = 128 blocks.
// h is double-buffered across steps (blocks read all of h_in, write h_out slice).
__global__ void __launch_bounds__(256) lstm_step_kernel(int t) {
    const float* __restrict__ hin = g_h2[t & 1];
    float* __restrict__ hout = g_h2[(t + 1) & 1];
    int warp = threadIdx.x >> 5, lane = threadIdx.x & 31;
    int j0 = blockIdx.x * 32 + warp * 4;

    float acc[4][4][4];  // [jj][gate][batch]
#pragma unroll
    for (int jj = 0; jj < 4; jj++)
#pragma unroll
        for (int g = 0; g < 4; g++)
#pragma unroll
            for (int b = 0; b < 4; b++) acc[jj][g][b] = 0.f;

#pragma unroll 1
    for (int ch = 0; ch < 16; ch++) {
        int k = ch * 256 + lane * 8;
        // h values for this k-slice, all 4 batches (L1-resident, 64KB total)
        float4 hv[4][2];
#pragma unroll
        for (int b = 0; b < 4; b++) {
            hv[b][0] = *(const float4*)(hin + b * LSTM_H + k);
            hv[b][1] = *(const float4*)(hin + b * LSTM_H + k + 4);
        }
#pragma unroll
        for (int jj = 0; jj < 4; jj++) {
#pragma unroll
            for (int g = 0; g < 4; g++) {
                size_t row = (size_t)(g * LSTM_H + j0 + jj) * LSTM_H;
                float4 wraw = *(const float4*)(g_Whh_h + row + k);  // 8 halves
                const __half2* wh = (const __half2*)&wraw;
                float2 w0 = __half22float2(wh[0]);
                float2 w1 = __half22float2(wh[1]);
                float2 w2 = __half22float2(wh[2]);
                float2 w3 = __half22float2(wh[3]);
#pragma unroll
                for (int b = 0; b < 4; b++) {
                    float s = acc[jj][g][b];
                    s += w0.x * hv[b][0].x;
                    s += w0.y * hv[b][0].y;
                    s += w1.x * hv[b][0].z;
                    s += w1.y * hv[b][0].w;
                    s += w2.x * hv[b][1].x;
                    s += w2.y * hv[b][1].y;
                    s += w3.x * hv[b][1].z;
                    s += w3.y * hv[b][1].w;
                    acc[jj][g][b] = s;
                }
            }
        }
    }

    // full butterfly reduction: every lane ends with all 64 totals
#pragma unroll
    for (int jj = 0; jj < 4; jj++)
#pragma unroll
        for (int g = 0; g < 4; g++)
#pragma unroll
            for (int b = 0; b < 4; b++) {
                float v = acc[jj][g][b];
#pragma unroll
                for (int off = 16; off; off >>= 1)
                    v += __shfl_xor_sync(0xffffffffu, v, off);
                acc[jj][g][b] = v;
            }

    // lanes 0..15: lane = jj*4 + b does the cell update for (j0+jj, batch b)
    if (lane < 16) {
        float gi = 0.f, gf = 0.f, gg = 0.f, go = 0.f;
#pragma unroll
        for (int jj = 0; jj < 4; jj++)
#pragma unroll
            for (int b = 0; b < 4; b++) {
                bool m = (lane == jj * 4 + b);
                gi = m ? acc[jj][0][b] : gi;
                gf = m ? acc[jj][1][b] : gf;
                gg = m ? acc[jj][2][b] : gg;
                go = m ? acc[jj][3][b] : go;
            }
        int jj = lane >> 2, b = lane & 3;
        int j = j0 + jj;
        const float* xp = g_xproj + (size_t)t * BB * GATES + (size_t)b * GATES;
        gi += xp[j];
        gf += xp[LSTM_H + j];
        gg += xp[2 * LSTM_H + j];
        go += xp[3 * LSTM_H + j];
        float c = g_c[b * LSTM_H + j];
        float si = 1.f / (1.f + expf(-gi));
        float sf = 1.f / (1.f + expf(-gf));
        float so = 1.f / (1.f + expf(-go));
        c = sf * c + si * tanhf(gg);
        g_c[b * LSTM_H + j] = c;
        hout[b * LSTM_H + j] = so * tanhf(c);
    }
}

// ---------- 7) final FC: out[b,n] = h[b, n*128:(n+1)*128] . fc_W + fc_b ----------
__global__ void final_fc_kernel(const float* __restrict__ fcW,
                                const float* __restrict__ fcb,
                                float* __restrict__ out) {
    int tid = threadIdx.x;  // 128
    int b = tid >> 5, n = tid & 31;
    const float* hp = g_h2[0] + (size_t)b * LSTM_H + n * 128;  // t=31 writes buf 0
    float s = fcb[0];
#pragma unroll 8
    for (int l = 0; l < 128; l++) s += hp[l] * fcW[l];
    out[tid] = s;
}

extern "C" void kernel_launch(void* const* d_in, const int* in_sizes, int n_in,
                              void* d_out, int out_size) {
    const float* x    = (const float*)d_in[0];
    const int*   ei   = (const int*)d_in[1];
    const float* ln_g = (const float*)d_in[2];
    const float* ln_b = (const float*)d_in[3];
    const float* W1   = (const float*)d_in[4];
    const float* b1   = (const float*)d_in[5];
    const float* W2   = (const float*)d_in[6];
    const float* b2   = (const float*)d_in[7];
    const float* W_ih = (const float*)d_in[8];
    const float* b_ih = (const float*)d_in[9];
    const float* W_hh = (const float*)d_in[10];
    const float* b_hh = (const float*)d_in[11];
    const float* fc_W = (const float*)d_in[12];
    const float* fc_b = (const float*)d_in[13];
    float* out = (float*)d_out;

    build_adj_kernel<<<1, 256>>>(ei);
    gcn_kernel<<<128, 256>>>(x, ln_g, ln_b, W1, b1, W2, b2);
    convert_whh_kernel<<<65536, 256>>>(W_hh);   // 67M elems / 4 per thread
    xproj_gemm_kernel<<<128, 256>>>(W_ih, b_ih, b_hh);
    init_hc_kernel<<<128, 256>>>();
    for (int t = 0; t < TT; t++) {
        lstm_step_kernel<<<128, 256>>>(t);
    }
    final_fc_kernel<<<1, 128>>>(fc_W, fc_b, out);
}

// round 3
// speedup vs baseline: 1.2350x; 1.2350x over previous
#include <cuda_runtime.h>
#include <cuda_fp16.h>
#include <cstdint>

// Problem constants
#define BB 4
#define TT 32
#define NN 32
#define FF 16
#define GH 64
#define LSTM_IN 2048     // NN*GH
#define LSTM_H 4096
#define GATES 16384      // 4*LSTM_H
#define E_EDGES 256

// Scratch (device globals; no dynamic allocation allowed)
__device__ float g_A[NN * NN];
__device__ float g_seq[BB * TT * LSTM_IN];            // 1 MB
__device__ float g_xproj[TT * BB * GATES];            // 8 MB
__device__ float g_h2[2][BB * LSTM_H];                // double-buffered hidden
__device__ float g_c[BB * LSTM_H];
__device__ __half g_Whh_h[(size_t)GATES * LSTM_H];    // 128 MiB fp16 weights

// ---------- packed f32x2 helpers (sm_103a FFMA2 path) ----------
__device__ __forceinline__ unsigned long long pack2(float lo, float hi) {
    unsigned long long r;
    unsigned int l = __float_as_uint(lo), h = __float_as_uint(hi);
    asm("mov.b64 %0, {%1, %2};" : "=l"(r) : "r"(l), "r"(h));
    return r;
}
__device__ __forceinline__ void ffma2(unsigned long long& d,
                                      unsigned long long a,
                                      unsigned long long b) {
    asm("fma.rn.f32x2 %0, %1, %2, %0;" : "+l"(d) : "l"(a), "l"(b));
}
__device__ __forceinline__ float2 unpack2(unsigned long long v) {
    unsigned int l, h;
    asm("mov.b64 {%0, %1}, %2;" : "=r"(l), "=r"(h) : "l"(v));
    float2 r;
    r.x = __uint_as_float(l);
    r.y = __uint_as_float(h);
    return r;
}

// ---------- 1) adjacency build (handles int32 or int64 edge_index) ----------
__global__ void build_adj_kernel(const int* __restrict__ ei32) {
    __shared__ int is32flag;
    __shared__ int deg[NN];
    __shared__ float dinv[NN];
    __shared__ float As[NN * NN];
    int tid = threadIdx.x;
    if (tid == 0) is32flag = 0;
    for (int i = tid; i < NN; i += blockDim.x) deg[i] = 1;  // self loop
    for (int i = tid; i < NN * NN; i += blockDim.x) As[i] = 0.f;
    __syncthreads();
    int any = 0;
    for (int w = tid * 2 + 1; w < 512; w += blockDim.x * 2) any |= ei32[w];
    if (any) atomicOr(&is32flag, 1);
    __syncthreads();
    const int is32 = is32flag;
    for (int e = tid; e < E_EDGES; e += blockDim.x) {
        int dst = is32 ? ei32[E_EDGES + e] : ei32[2 * (E_EDGES + e)];
        atomicAdd(&deg[dst], 1);
    }
    __syncthreads();
    for (int i = tid; i < NN; i += blockDim.x) dinv[i] = rsqrtf((float)deg[i]);
    __syncthreads();
    for (int e = tid; e < E_EDGES; e += blockDim.x) {
        int src = is32 ? ei32[e] : ei32[2 * e];
        int dst = is32 ? ei32[E_EDGES + e] : ei32[2 * (E_EDGES + e)];
        atomicAdd(&As[dst * NN + src], dinv[src] * dinv[dst]);
    }
    for (int n = tid; n < NN; n += blockDim.x)
        atomicAdd(&As[n * NN + n], dinv[n] * dinv[n]);
    __syncthreads();
    for (int i = tid; i < NN * NN; i += blockDim.x) g_A[i] = As[i];
}

// ---------- 2) LayerNorm + GCN x2 -> seq[bt][n*GH+g] ----------
__global__ void __launch_bounds__(256) gcn_kernel(
    const float* __restrict__ x, const float* __restrict__ ln_g,
    const float* __restrict__ ln_b, const float* __restrict__ W1,
    const float* __restrict__ b1, const float* __restrict__ W2,
    const float* __restrict__ b2) {
    __shared__ float xln[NN * FF];
    __shared__ float bufA[NN * GH];
    __shared__ float bufB[NN * GH];
    __shared__ float As[NN * NN];
    int tid = threadIdx.x;
    int bt = blockIdx.x;  // b*TT + t
    const float* xp = x + (size_t)bt * NN * FF;

    for (int i = tid; i < NN * NN; i += 256) As[i] = g_A[i];
    if (tid < NN) {
        float v[FF];
        float mu = 0.f;
#pragma unroll
        for (int f = 0; f < FF; f++) { v[f] = xp[tid * FF + f]; mu += v[f]; }
        mu *= (1.f / FF);
        float var = 0.f;
#pragma unroll
        for (int f = 0; f < FF; f++) { float d = v[f] - mu; var += d * d; }
        var *= (1.f / FF);
        float r = rsqrtf(var + 1e-5f);
#pragma unroll
        for (int f = 0; f < FF; f++)
            xln[tid * FF + f] = (v[f] - mu) * r * ln_g[f] + ln_b[f];
    }
    __syncthreads();
    for (int o = tid; o < NN * GH; o += 256) {
        int n = o >> 6, g = o & 63;
        float s = 0.f;
#pragma unroll
        for (int f = 0; f < FF; f++) s += xln[n * FF + f] * W1[f * GH + g];
        bufA[o] = s;
    }
    __syncthreads();
    for (int o = tid; o < NN * GH; o += 256) {
        int n = o >> 6, g = o & 63;
        float s = b1[g];
#pragma unroll 8
        for (int sn = 0; sn < NN; sn++) s += As[n * NN + sn] * bufA[sn * GH + g];
        bufB[o] = s;
    }
    __syncthreads();
    for (int o = tid; o < NN * GH; o += 256) {
        int n = o >> 6, g = o & 63;
        float s = 0.f;
#pragma unroll 8
        for (int f = 0; f < GH; f++) s += bufB[n * GH + f] * W2[f * GH + g];
        bufA[o] = s;
    }
    __syncthreads();
    for (int o = tid; o < NN * GH; o += 256) {
        int n = o >> 6, g = o & 63;
        float s = b2[g];
#pragma unroll 8
        for (int sn = 0; sn < NN; sn++) s += As[n * NN + sn] * bufA[sn * GH + g];
        g_seq[(size_t)bt * LSTM_IN + o] = s;
    }
}

// ---------- 3) x_proj = seq @ W_ih^T + (b_ih + b_hh) ----------
// M=128 (bt), N=16384 (gates), K=2048. Tile 128x64 per block, grid 256.
__global__ void __launch_bounds__(256) xproj_gemm_kernel(
    const float* __restrict__ Wih, const float* __restrict__ b_ih,
    const float* __restrict__ b_hh) {
    __shared__ float Ss[16][128];
    __shared__ float Ws[16][64];
    int tid = threadIdx.x;
    int tx = tid & 15, ty = tid >> 4;
    int gbase = blockIdx.x * 64;
    unsigned long long acc[8][2];
#pragma unroll
    for (int i = 0; i < 8; i++) { acc[i][0] = 0ull; acc[i][1] = 0ull; }

    for (int kc = 0; kc < 2048; kc += 16) {
        {
            // Ss: 128 rows x 16 k = 512 float4, 2 per thread
#pragma unroll
            for (int i = 0; i < 2; i++) {
                int idx = tid + i * 256;
                int row = idx >> 2, c = idx & 3;
                float4 v = *(const float4*)&g_seq[(size_t)row * 2048 + kc + c * 4];
                Ss[c * 4 + 0][row] = v.x;
                Ss[c * 4 + 1][row] = v.y;
                Ss[c * 4 + 2][row] = v.z;
                Ss[c * 4 + 3][row] = v.w;
            }
            // Ws: 64 rows x 16 k = 256 float4, 1 per thread
            int row = tid >> 2, c = tid & 3;
            float4 w = *(const float4*)(Wih + (size_t)(gbase + row) * 2048 + kc + c * 4);
            Ws[c * 4 + 0][row] = w.x;
            Ws[c * 4 + 1][row] = w.y;
            Ws[c * 4 + 2][row] = w.z;
            Ws[c * 4 + 3][row] = w.w;
        }
        __syncthreads();
#pragma unroll
        for (int kk = 0; kk < 16; kk++) {
            float4 a0 = *(float4*)&Ss[kk][ty * 8];
            float4 a1 = *(float4*)&Ss[kk][ty * 8 + 4];
            float4 b0 = *(float4*)&Ws[kk][tx * 4];
            unsigned long long bp0 = pack2(b0.x, b0.y);
            unsigned long long bp1 = pack2(b0.z, b0.w);
            float av[8] = {a0.x, a0.y, a0.z, a0.w, a1.x, a1.y, a1.z, a1.w};
#pragma unroll
            for (int i = 0; i < 8; i++) {
                unsigned long long ap = pack2(av[i], av[i]);
                ffma2(acc[i][0], ap, bp0);
                ffma2(acc[i][1], ap, bp1);
            }
        }
        __syncthreads();
    }
#pragma unroll
    for (int i = 0; i < 8; i++) {
        int m = ty * 8 + i;
        int t = m & 31, b = m >> 5;
        int g = gbase + tx * 4;
        float* outp = g_xproj + (size_t)t * BB * GATES + (size_t)b * GATES + g;
        float2 v0 = unpack2(acc[i][0]);
        float2 v1 = unpack2(acc[i][1]);
        outp[0] = v0.x + b_ih[g] + b_hh[g];
        outp[1] = v0.y + b_ih[g + 1] + b_hh[g + 1];
        outp[2] = v1.x + b_ih[g + 2] + b_hh[g + 2];
        outp[3] = v1.y + b_ih[g + 3] + b_hh[g + 3];
    }
}

// ---------- 4) convert W_hh -> fp16 (once per launch; halves step traffic) ----
__global__ void __launch_bounds__(256) convert_whh_kernel(const float* __restrict__ Whh) {
    size_t i = ((size_t)blockIdx.x * 256 + threadIdx.x) * 4;  // 4 elems/thread
    float4 v = *(const float4*)(Whh + i);
    __half2* out = (__half2*)(g_Whh_h + i);
    out[0] = __floats2half2_rn(v.x, v.y);
    out[1] = __floats2half2_rn(v.z, v.w);
}

// ---------- 5) init h,c ----------
__global__ void init_hc_kernel() {
    int idx = blockIdx.x * 256 + threadIdx.x;  // < 32768
    if (idx < BB * LSTM_H) g_h2[0][idx] = 0.f;
    else g_c[idx - BB * LSTM_H] = 0.f;
}

// ---------- 6) fused LSTM step: warp-per-row GEMV (fp16 W, f32x2 FFMA2) ------
// Block = 8 warps: warp = jrel*4 + gate  (2 j values x 4 gates).
// Grid = 2048 blocks -> 16384 warps (one per W_hh row), 4 batches per warp.
__global__ void __launch_bounds__(256) lstm_step_kernel(int t) {
    __shared__ float s_g[8][4];  // [warp][batch]
    const float* __restrict__ hin = g_h2[t & 1];
    float* __restrict__ hout = g_h2[(t + 1) & 1];
    int warp = threadIdx.x >> 5, lane = threadIdx.x & 31;
    int jrel = warp >> 2, gate = warp & 3;
    int j = blockIdx.x * 2 + jrel;
    const __half* Wr = g_Whh_h + (size_t)(gate * LSTM_H + j) * LSTM_H;
    const ulonglong2* __restrict__ hp = (const ulonglong2*)hin;  // f32 pairs

    unsigned long long acc0 = 0ull, acc1 = 0ull, acc2 = 0ull, acc3 = 0ull;
#pragma unroll 4
    for (int kk = 0; kk < 16; kk++) {
        int k = kk * 256 + lane * 8;  // 8 halves / 8 floats per lane
        float4 wraw = *(const float4*)(Wr + k);  // 8 halves
        const __half2* wh = (const __half2*)&wraw;
        unsigned long long wp[4];
#pragma unroll
        for (int p = 0; p < 4; p++) {
            float2 wf = __half22float2(wh[p]);
            wp[p] = pack2(wf.x, wf.y);
        }
        int hq = k >> 1;  // index into ulonglong2 (4 floats each)
#pragma unroll
        for (int b = 0; b < 4; b++) {
            ulonglong2 h01 = hp[(b * LSTM_H >> 2) + (hq >> 1)];
            ulonglong2 h23 = hp[(b * LSTM_H >> 2) + (hq >> 1) + 1];
            unsigned long long* a = (b == 0) ? &acc0 : (b == 1) ? &acc1
                                  : (b == 2) ? &acc2 : &acc3;
            ffma2(*a, wp[0], h01.x);
            ffma2(*a, wp[1], h01.y);
            ffma2(*a, wp[2], h23.x);
            ffma2(*a, wp[3], h23.y);
        }
    }
    float v[4];
    {
        float2 f0 = unpack2(acc0), f1 = unpack2(acc1),
               f2 = unpack2(acc2), f3 = unpack2(acc3);
        v[0] = f0.x + f0.y; v[1] = f1.x + f1.y;
        v[2] = f2.x + f2.y; v[3] = f3.x + f3.y;
    }
#pragma unroll
    for (int b = 0; b < 4; b++) {
#pragma unroll
        for (int off = 16; off; off >>= 1)
            v[b] += __shfl_xor_sync(0xffffffffu, v[b], off);
    }
    if (lane == 0) {
        s_g[warp][0] = v[0]; s_g[warp][1] = v[1];
        s_g[warp][2] = v[2]; s_g[warp][3] = v[3];
    }
    __syncthreads();
    if (threadIdx.x < 8) {
        int jr = threadIdx.x >> 2, b = threadIdx.x & 3;
        int jj = blockIdx.x * 2 + jr;
        const float* xp = g_xproj + (size_t)t * BB * GATES + (size_t)b * GATES;
        float gi = s_g[jr * 4 + 0][b] + xp[jj];
        float gf = s_g[jr * 4 + 1][b] + xp[LSTM_H + jj];
        float gg = s_g[jr * 4 + 2][b] + xp[2 * LSTM_H + jj];
        float go = s_g[jr * 4 + 3][b] + xp[3 * LSTM_H + jj];
        float c = g_c[b * LSTM_H + jj];
        float si = 1.f / (1.f + expf(-gi));
        float sf = 1.f / (1.f + expf(-gf));
        float so = 1.f / (1.f + expf(-go));
        c = sf * c + si * tanhf(gg);
        g_c[b * LSTM_H + jj] = c;
        hout[b * LSTM_H + jj] = so * tanhf(c);
    }
}

// ---------- 7) final FC ----------
__global__ void final_fc_kernel(const float* __restrict__ fcW,
                                const float* __restrict__ fcb,
                                float* __restrict__ out) {
    int tid = threadIdx.x;  // 128
    int b = tid >> 5, n = tid & 31;
    const float* hp = g_h2[0] + (size_t)b * LSTM_H + n * 128;  // t=31 writes buf 0
    float s = fcb[0];
#pragma unroll 8
    for (int l = 0; l < 128; l++) s += hp[l] * fcW[l];
    out[tid] = s;
}

extern "C" void kernel_launch(void* const* d_in, const int* in_sizes, int n_in,
                              void* d_out, int out_size) {
    const float* x    = (const float*)d_in[0];
    const int*   ei   = (const int*)d_in[1];
    const float* ln_g = (const float*)d_in[2];
    const float* ln_b = (const float*)d_in[3];
    const float* W1   = (const float*)d_in[4];
    const float* b1   = (const float*)d_in[5];
    const float* W2   = (const float*)d_in[6];
    const float* b2   = (const float*)d_in[7];
    const float* W_ih = (const float*)d_in[8];
    const float* b_ih = (const float*)d_in[9];
    const float* W_hh = (const float*)d_in[10];
    const float* b_hh = (const float*)d_in[11];
    const float* fc_W = (const float*)d_in[12];
    const float* fc_b = (const float*)d_in[13];
    float* out = (float*)d_out;

    build_adj_kernel<<<1, 256>>>(ei);
    gcn_kernel<<<128, 256>>>(x, ln_g, ln_b, W1, b1, W2, b2);
    convert_whh_kernel<<<65536, 256>>>(W_hh);   // 67M elems / 4 per thread
    xproj_gemm_kernel<<<256, 256>>>(W_ih, b_ih, b_hh);
    init_hc_kernel<<<128, 256>>>();
    for (int t = 0; t < TT; t++) {
        lstm_step_kernel<<<2048, 256>>>(t);
    }
    final_fc_kernel<<<1, 128>>>(fc_W, fc_b, out);
}

// round 4
// speedup vs baseline: 2.0917x; 1.6936x over previous
#include <cuda_runtime.h>
#include <cuda_fp16.h>
#include <cstdint>

// Problem constants
#define BB 4
#define TT 32
#define NN 32
#define FF 16
#define GH 64
#define LSTM_IN 2048     // NN*GH
#define LSTM_H 4096
#define GATES 16384      // 4*LSTM_H
#define E_EDGES 256

// Scratch (device globals; no dynamic allocation allowed)
__device__ float g_A[NN * NN];
__device__ float g_seq[BB * TT * LSTM_IN];            // 1 MB
__device__ float g_xproj[TT * BB * GATES];            // 8 MB
__device__ float g_h2[2][BB * LSTM_H];                // double-buffered hidden
__device__ float g_c[BB * LSTM_H];
__device__ __half g_Whh_h[(size_t)GATES * LSTM_H];    // 128 MiB fp16 weights

// ---------- packed f32x2 helpers (sm_103a FFMA2 path) ----------
__device__ __forceinline__ unsigned long long pack2(float lo, float hi) {
    unsigned long long r;
    unsigned int l = __float_as_uint(lo), h = __float_as_uint(hi);
    asm("mov.b64 %0, {%1, %2};" : "=l"(r) : "r"(l), "r"(h));
    return r;
}
__device__ __forceinline__ void ffma2(unsigned long long& d,
                                      unsigned long long a,
                                      unsigned long long b) {
    asm("fma.rn.f32x2 %0, %1, %2, %0;" : "+l"(d) : "l"(a), "l"(b));
}
__device__ __forceinline__ float2 unpack2(unsigned long long v) {
    unsigned int l, h;
    asm("mov.b64 {%0, %1}, %2;" : "=r"(l), "=r"(h) : "l"(v));
    float2 r;
    r.x = __uint_as_float(l);
    r.y = __uint_as_float(h);
    return r;
}

// ---------- 1) adjacency build (handles int32 or int64 edge_index) ----------
__global__ void build_adj_kernel(const int* __restrict__ ei32) {
    __shared__ int is32flag;
    __shared__ int deg[NN];
    __shared__ float dinv[NN];
    __shared__ float As[NN * NN];
    int tid = threadIdx.x;
    if (tid == 0) is32flag = 0;
    for (int i = tid; i < NN; i += blockDim.x) deg[i] = 1;  // self loop
    for (int i = tid; i < NN * NN; i += blockDim.x) As[i] = 0.f;
    __syncthreads();
    int any = 0;
    for (int w = tid * 2 + 1; w < 512; w += blockDim.x * 2) any |= ei32[w];
    if (any) atomicOr(&is32flag, 1);
    __syncthreads();
    const int is32 = is32flag;
    for (int e = tid; e < E_EDGES; e += blockDim.x) {
        int dst = is32 ? ei32[E_EDGES + e] : ei32[2 * (E_EDGES + e)];
        atomicAdd(&deg[dst], 1);
    }
    __syncthreads();
    for (int i = tid; i < NN; i += blockDim.x) dinv[i] = rsqrtf((float)deg[i]);
    __syncthreads();
    for (int e = tid; e < E_EDGES; e += blockDim.x) {
        int src = is32 ? ei32[e] : ei32[2 * e];
        int dst = is32 ? ei32[E_EDGES + e] : ei32[2 * (E_EDGES + e)];
        atomicAdd(&As[dst * NN + src], dinv[src] * dinv[dst]);
    }
    for (int n = tid; n < NN; n += blockDim.x)
        atomicAdd(&As[n * NN + n], dinv[n] * dinv[n]);
    __syncthreads();
    for (int i = tid; i < NN * NN; i += blockDim.x) g_A[i] = As[i];
}

// ---------- 2) LayerNorm + GCN x2 -> seq[bt][n*GH+g] ----------
__global__ void __launch_bounds__(256) gcn_kernel(
    const float* __restrict__ x, const float* __restrict__ ln_g,
    const float* __restrict__ ln_b, const float* __restrict__ W1,
    const float* __restrict__ b1, const float* __restrict__ W2,
    const float* __restrict__ b2) {
    __shared__ float xln[NN * FF];
    __shared__ float bufA[NN * GH];
    __shared__ float bufB[NN * GH];
    __shared__ float As[NN * NN];
    int tid = threadIdx.x;
    int bt = blockIdx.x;  // b*TT + t
    const float* xp = x + (size_t)bt * NN * FF;

    for (int i = tid; i < NN * NN; i += 256) As[i] = g_A[i];
    if (tid < NN) {
        float v[FF];
        float mu = 0.f;
#pragma unroll
        for (int f = 0; f < FF; f++) { v[f] = xp[tid * FF + f]; mu += v[f]; }
        mu *= (1.f / FF);
        float var = 0.f;
#pragma unroll
        for (int f = 0; f < FF; f++) { float d = v[f] - mu; var += d * d; }
        var *= (1.f / FF);
        float r = rsqrtf(var + 1e-5f);
#pragma unroll
        for (int f = 0; f < FF; f++)
            xln[tid * FF + f] = (v[f] - mu) * r * ln_g[f] + ln_b[f];
    }
    __syncthreads();
    for (int o = tid; o < NN * GH; o += 256) {
        int n = o >> 6, g = o & 63;
        float s = 0.f;
#pragma unroll
        for (int f = 0; f < FF; f++) s += xln[n * FF + f] * W1[f * GH + g];
        bufA[o] = s;
    }
    __syncthreads();
    for (int o = tid; o < NN * GH; o += 256) {
        int n = o >> 6, g = o & 63;
        float s = b1[g];
#pragma unroll 8
        for (int sn = 0; sn < NN; sn++) s += As[n * NN + sn] * bufA[sn * GH + g];
        bufB[o] = s;
    }
    __syncthreads();
    for (int o = tid; o < NN * GH; o += 256) {
        int n = o >> 6, g = o & 63;
        float s = 0.f;
#pragma unroll 8
        for (int f = 0; f < GH; f++) s += bufB[n * GH + f] * W2[f * GH + g];
        bufA[o] = s;
    }
    __syncthreads();
    for (int o = tid; o < NN * GH; o += 256) {
        int n = o >> 6, g = o & 63;
        float s = b2[g];
#pragma unroll 8
        for (int sn = 0; sn < NN; sn++) s += As[n * NN + sn] * bufA[sn * GH + g];
        g_seq[(size_t)bt * LSTM_IN + o] = s;
    }
}

// ---------- 3) x_proj = seq @ W_ih^T + (b_ih + b_hh) ----------
// M=128 (bt), N=16384 (gates), K=2048. Tile 64x64, grid (256, 2) = 512 blocks.
__global__ void __launch_bounds__(256) xproj_gemm_kernel(
    const float* __restrict__ Wih, const float* __restrict__ b_ih,
    const float* __restrict__ b_hh) {
    __shared__ float Ss[16][64];
    __shared__ float Ws[16][64];
    int tid = threadIdx.x;
    int tx = tid & 15, ty = tid >> 4;
    int gbase = blockIdx.x * 64;
    int mbase = blockIdx.y * 64;
    unsigned long long acc[4][2];
#pragma unroll
    for (int i = 0; i < 4; i++) { acc[i][0] = 0ull; acc[i][1] = 0ull; }

    for (int kc = 0; kc < 2048; kc += 16) {
        {
            int row = tid >> 2, c = tid & 3;  // 64 rows x 4 float4
            float4 v = *(const float4*)&g_seq[(size_t)(mbase + row) * 2048 + kc + c * 4];
            Ss[c * 4 + 0][row] = v.x;
            Ss[c * 4 + 1][row] = v.y;
            Ss[c * 4 + 2][row] = v.z;
            Ss[c * 4 + 3][row] = v.w;
            float4 w = *(const float4*)(Wih + (size_t)(gbase + row) * 2048 + kc + c * 4);
            Ws[c * 4 + 0][row] = w.x;
            Ws[c * 4 + 1][row] = w.y;
            Ws[c * 4 + 2][row] = w.z;
            Ws[c * 4 + 3][row] = w.w;
        }
        __syncthreads();
#pragma unroll
        for (int kk = 0; kk < 16; kk++) {
            float4 a = *(float4*)&Ss[kk][ty * 4];
            float4 b = *(float4*)&Ws[kk][tx * 4];
            unsigned long long bp0 = pack2(b.x, b.y);
            unsigned long long bp1 = pack2(b.z, b.w);
            float av[4] = {a.x, a.y, a.z, a.w};
#pragma unroll
            for (int i = 0; i < 4; i++) {
                unsigned long long ap = pack2(av[i], av[i]);
                ffma2(acc[i][0], ap, bp0);
                ffma2(acc[i][1], ap, bp1);
            }
        }
        __syncthreads();
    }
#pragma unroll
    for (int i = 0; i < 4; i++) {
        int m = mbase + ty * 4 + i;
        int t = m & 31, b = m >> 5;
        int g = gbase + tx * 4;
        float* outp = g_xproj + (size_t)t * BB * GATES + (size_t)b * GATES + g;
        float2 v0 = unpack2(acc[i][0]);
        float2 v1 = unpack2(acc[i][1]);
        outp[0] = v0.x + b_ih[g] + b_hh[g];
        outp[1] = v0.y + b_ih[g + 1] + b_hh[g + 1];
        outp[2] = v1.x + b_ih[g + 2] + b_hh[g + 2];
        outp[3] = v1.y + b_ih[g + 3] + b_hh[g + 3];
    }
}

// ---------- 4) convert W_hh -> fp16 (once per launch; halves step traffic) ----
__global__ void __launch_bounds__(256) convert_whh_kernel(const float* __restrict__ Whh) {
    size_t i = ((size_t)blockIdx.x * 256 + threadIdx.x) * 4;  // 4 elems/thread
    float4 v = *(const float4*)(Whh + i);
    __half2* out = (__half2*)(g_Whh_h + i);
    out[0] = __floats2half2_rn(v.x, v.y);
    out[1] = __floats2half2_rn(v.z, v.w);
}

// ---------- 5) init h,c ----------
__global__ void init_hc_kernel() {
    int idx = blockIdx.x * 256 + threadIdx.x;  // < 32768
    if (idx < BB * LSTM_H) g_h2[0][idx] = 0.f;
    else g_c[idx - BB * LSTM_H] = 0.f;
}

// ---------- 6) fused LSTM step ------------------------------------------------
// Warp = one hidden index j: computes all 4 gate rows x 4 batches (16 dots).
// Weight rows are read once; h (64KB, L1-resident) amortized across 4 gates.
// Block = 4 warps, grid = 1024 -> 4096 warps. No smem, no cross-warp sync.
__global__ void __launch_bounds__(128) lstm_step_kernel(int t) {
    const float* __restrict__ hin = g_h2[t & 1];
    float* __restrict__ hout = g_h2[(t + 1) & 1];
    int warp = threadIdx.x >> 5, lane = threadIdx.x & 31;
    int j = blockIdx.x * 4 + warp;

    unsigned long long acc[4][4];  // [gate][batch] packed f32x2
#pragma unroll
    for (int g = 0; g < 4; g++)
#pragma unroll
        for (int b = 0; b < 4; b++) acc[g][b] = 0ull;

#pragma unroll 4
    for (int kk = 0; kk < 16; kk++) {
        int k = kk * 256 + lane * 8;  // 8 halves/floats per lane
        // 4 gate-row weight fragments (DRAM-streaming part)
        float4 wraw[4];
#pragma unroll
        for (int g = 0; g < 4; g++)
            wraw[g] = *(const float4*)(g_Whh_h + ((size_t)(g * LSTM_H + j)) * LSTM_H + k);
        // convert to packed f32x2 once, reuse across 4 batches
        unsigned long long wp[4][4];
#pragma unroll
        for (int g = 0; g < 4; g++) {
            const __half2* wh = (const __half2*)&wraw[g];
#pragma unroll
            for (int p = 0; p < 4; p++) {
                float2 wf = __half22float2(wh[p]);
                wp[g][p] = pack2(wf.x, wf.y);
            }
        }
#pragma unroll
        for (int b = 0; b < 4; b++) {
            const ulonglong2* hp = (const ulonglong2*)(hin + b * LSTM_H + k);
            ulonglong2 h01 = hp[0];
            ulonglong2 h23 = hp[1];
#pragma unroll
            for (int g = 0; g < 4; g++) {
                ffma2(acc[g][b], wp[g][0], h01.x);
                ffma2(acc[g][b], wp[g][1], h01.y);
                ffma2(acc[g][b], wp[g][2], h23.x);
                ffma2(acc[g][b], wp[g][3], h23.y);
            }
        }
    }

    // fold f32x2 -> scalar, butterfly so every lane holds all 16 totals
    float v[4][4];
#pragma unroll
    for (int g = 0; g < 4; g++)
#pragma unroll
        for (int b = 0; b < 4; b++) {
            float2 f = unpack2(acc[g][b]);
            float s = f.x + f.y;
#pragma unroll
            for (int off = 16; off; off >>= 1)
                s += __shfl_xor_sync(0xffffffffu, s, off);
            v[g][b] = s;
        }

    if (lane < 4) {
        int b = lane;
        const float* xp = g_xproj + (size_t)t * BB * GATES + (size_t)b * GATES;
        float gi = v[0][b] + xp[j];
        float gf = v[1][b] + xp[LSTM_H + j];
        float gg = v[2][b] + xp[2 * LSTM_H + j];
        float go = v[3][b] + xp[3 * LSTM_H + j];
        float c = g_c[b * LSTM_H + j];
        float si = 1.f / (1.f + expf(-gi));
        float sf = 1.f / (1.f + expf(-gf));
        float so = 1.f / (1.f + expf(-go));
        c = sf * c + si * tanhf(gg);
        g_c[b * LSTM_H + j] = c;
        hout[b * LSTM_H + j] = so * tanhf(c);
    }
}

// ---------- 7) final FC ----------
__global__ void final_fc_kernel(const float* __restrict__ fcW,
                                const float* __restrict__ fcb,
                                float* __restrict__ out) {
    int tid = threadIdx.x;  // 128
    int b = tid >> 5, n = tid & 31;
    const float* hp = g_h2[0] + (size_t)b * LSTM_H + n * 128;  // t=31 writes buf 0
    float s = fcb[0];
#pragma unroll 8
    for (int l = 0; l < 128; l++) s += hp[l] * fcW[l];
    out[tid] = s;
}

extern "C" void kernel_launch(void* const* d_in, const int* in_sizes, int n_in,
                              void* d_out, int out_size) {
    const float* x    = (const float*)d_in[0];
    const int*   ei   = (const int*)d_in[1];
    const float* ln_g = (const float*)d_in[2];
    const float* ln_b = (const float*)d_in[3];
    const float* W1   = (const float*)d_in[4];
    const float* b1   = (const float*)d_in[5];
    const float* W2   = (const float*)d_in[6];
    const float* b2   = (const float*)d_in[7];
    const float* W_ih = (const float*)d_in[8];
    const float* b_ih = (const float*)d_in[9];
    const float* W_hh = (const float*)d_in[10];
    const float* b_hh = (const float*)d_in[11];
    const float* fc_W = (const float*)d_in[12];
    const float* fc_b = (const float*)d_in[13];
    float* out = (float*)d_out;

    build_adj_kernel<<<1, 256>>>(ei);
    gcn_kernel<<<128, 256>>>(x, ln_g, ln_b, W1, b1, W2, b2);
    convert_whh_kernel<<<65536, 256>>>(W_hh);   // 67M elems / 4 per thread
    {
        dim3 grid(256, 2);
        xproj_gemm_kernel<<<grid, 256>>>(W_ih, b_ih, b_hh);
    }
    init_hc_kernel<<<128, 256>>>();
    for (int t = 0; t < TT; t++) {
        lstm_step_kernel<<<1024, 128>>>(t);
    }
    final_fc_kernel<<<1, 128>>>(fc_W, fc_b, out);
}

// round 5
// speedup vs baseline: 2.0932x; 1.0007x over previous
#include <cuda_runtime.h>
#include <cuda_fp16.h>
#include <cstdint>

// Problem constants
#define BB 4
#define TT 32
#define NN 32
#define FF 16
#define GH 64
#define LSTM_IN 2048     // NN*GH
#define LSTM_H 4096
#define GATES 16384      // 4*LSTM_H
#define E_EDGES 256

// Scratch (device globals; no dynamic allocation allowed)
__device__ float g_A[NN * NN];
__device__ __half g_seq_h[BB * TT * LSTM_IN];         // 512 KB fp16
__device__ float g_xproj[TT * BB * GATES];            // 8 MB
__device__ float g_h2[2][BB * LSTM_H];                // double-buffered hidden
__device__ float g_c[BB * LSTM_H];
__device__ __half g_Whh_h[(size_t)GATES * LSTM_H];    // 128 MiB fp16 weights
__device__ __half g_Wih_h[(size_t)GATES * LSTM_IN];   // 64 MiB fp16 weights

// ---------- packed f32x2 helpers ----------
__device__ __forceinline__ unsigned long long pack2(float lo, float hi) {
    unsigned long long r;
    unsigned int l = __float_as_uint(lo), h = __float_as_uint(hi);
    asm("mov.b64 %0, {%1, %2};" : "=l"(r) : "r"(l), "r"(h));
    return r;
}
__device__ __forceinline__ void ffma2(unsigned long long& d,
                                      unsigned long long a,
                                      unsigned long long b) {
    asm("fma.rn.f32x2 %0, %1, %2, %0;" : "+l"(d) : "l"(a), "l"(b));
}
__device__ __forceinline__ float2 unpack2(unsigned long long v) {
    unsigned int l, h;
    asm("mov.b64 {%0, %1}, %2;" : "=r"(l), "=r"(h) : "l"(v));
    float2 r;
    r.x = __uint_as_float(l);
    r.y = __uint_as_float(h);
    return r;
}

__device__ __forceinline__ uint32_t smem_u32(const void* p) {
    return (uint32_t)__cvta_generic_to_shared(p);
}
#define CP_ASYNC16(dst_u32, src_ptr) \
    asm volatile("cp.async.cg.shared.global [%0], [%1], 16;" :: "r"(dst_u32), "l"(src_ptr))
#define CP_COMMIT() asm volatile("cp.async.commit_group;" ::: "memory")
#define SWZ(x) ((x) ^ (((x) >> 3) & 0x70))

// ---------- 1) adjacency build (handles int32 or int64 edge_index) ----------
__global__ void build_adj_kernel(const int* __restrict__ ei32) {
    __shared__ int is32flag;
    __shared__ int deg[NN];
    __shared__ float dinv[NN];
    __shared__ float As[NN * NN];
    int tid = threadIdx.x;
    if (tid == 0) is32flag = 0;
    for (int i = tid; i < NN; i += blockDim.x) deg[i] = 1;  // self loop
    for (int i = tid; i < NN * NN; i += blockDim.x) As[i] = 0.f;
    __syncthreads();
    int any = 0;
    for (int w = tid * 2 + 1; w < 512; w += blockDim.x * 2) any |= ei32[w];
    if (any) atomicOr(&is32flag, 1);
    __syncthreads();
    const int is32 = is32flag;
    for (int e = tid; e < E_EDGES; e += blockDim.x) {
        int dst = is32 ? ei32[E_EDGES + e] : ei32[2 * (E_EDGES + e)];
        atomicAdd(&deg[dst], 1);
    }
    __syncthreads();
    for (int i = tid; i < NN; i += blockDim.x) dinv[i] = rsqrtf((float)deg[i]);
    __syncthreads();
    for (int e = tid; e < E_EDGES; e += blockDim.x) {
        int src = is32 ? ei32[e] : ei32[2 * e];
        int dst = is32 ? ei32[E_EDGES + e] : ei32[2 * (E_EDGES + e)];
        atomicAdd(&As[dst * NN + src], dinv[src] * dinv[dst]);
    }
    for (int n = tid; n < NN; n += blockDim.x)
        atomicAdd(&As[n * NN + n], dinv[n] * dinv[n]);
    __syncthreads();
    for (int i = tid; i < NN * NN; i += blockDim.x) g_A[i] = As[i];
}

// ---------- 2) LayerNorm + GCN x2 -> seq (fp16) ----------
__global__ void __launch_bounds__(256) gcn_kernel(
    const float* __restrict__ x, const float* __restrict__ ln_g,
    const float* __restrict__ ln_b, const float* __restrict__ W1,
    const float* __restrict__ b1, const float* __restrict__ W2,
    const float* __restrict__ b2) {
    __shared__ float xln[NN * FF];
    __shared__ float bufA[NN * GH];
    __shared__ float bufB[NN * GH];
    __shared__ float As[NN * NN];
    int tid = threadIdx.x;
    int bt = blockIdx.x;  // b*TT + t
    const float* xp = x + (size_t)bt * NN * FF;

    for (int i = tid; i < NN * NN; i += 256) As[i] = g_A[i];
    if (tid < NN) {
        float v[FF];
        float mu = 0.f;
#pragma unroll
        for (int f = 0; f < FF; f++) { v[f] = xp[tid * FF + f]; mu += v[f]; }
        mu *= (1.f / FF);
        float var = 0.f;
#pragma unroll
        for (int f = 0; f < FF; f++) { float d = v[f] - mu; var += d * d; }
        var *= (1.f / FF);
        float r = rsqrtf(var + 1e-5f);
#pragma unroll
        for (int f = 0; f < FF; f++)
            xln[tid * FF + f] = (v[f] - mu) * r * ln_g[f] + ln_b[f];
    }
    __syncthreads();
    for (int o = tid; o < NN * GH; o += 256) {
        int n = o >> 6, g = o & 63;
        float s = 0.f;
#pragma unroll
        for (int f = 0; f < FF; f++) s += xln[n * FF + f] * W1[f * GH + g];
        bufA[o] = s;
    }
    __syncthreads();
    for (int o = tid; o < NN * GH; o += 256) {
        int n = o >> 6, g = o & 63;
        float s = b1[g];
#pragma unroll 8
        for (int sn = 0; sn < NN; sn++) s += As[n * NN + sn] * bufA[sn * GH + g];
        bufB[o] = s;
    }
    __syncthreads();
    for (int o = tid; o < NN * GH; o += 256) {
        int n = o >> 6, g = o & 63;
        float s = 0.f;
#pragma unroll 8
        for (int f = 0; f < GH; f++) s += bufB[n * GH + f] * W2[f * GH + g];
        bufA[o] = s;
    }
    __syncthreads();
    for (int o = tid; o < NN * GH; o += 256) {
        int n = o >> 6, g = o & 63;
        float s = b2[g];
#pragma unroll 8
        for (int sn = 0; sn < NN; sn++) s += As[n * NN + sn] * bufA[sn * GH + g];
        g_seq_h[(size_t)bt * LSTM_IN + o] = __float2half_rn(s);
    }
}

// ---------- 3) converts ----------
__global__ void __launch_bounds__(256) convert_whh_kernel(const float* __restrict__ Whh) {
    size_t i = ((size_t)blockIdx.x * 256 + threadIdx.x) * 4;
    float4 v = *(const float4*)(Whh + i);
    __half2* out = (__half2*)(g_Whh_h + i);
    out[0] = __floats2half2_rn(v.x, v.y);
    out[1] = __floats2half2_rn(v.z, v.w);
}
__global__ void __launch_bounds__(256) convert_wih_kernel(const float* __restrict__ Wih) {
    size_t i = ((size_t)blockIdx.x * 256 + threadIdx.x) * 4;
    float4 v = *(const float4*)(Wih + i);
    __half2* out = (__half2*)(g_Wih_h + i);
    out[0] = __floats2half2_rn(v.x, v.y);
    out[1] = __floats2half2_rn(v.z, v.w);
}

// ---------- 4) x_proj GEMM on tensor cores (HMMA) -----------------------------
// C[m=128 bt][n=16384 gates] = A[128,2048]h @ B[16384,2048]h^T + bias, fp32 acc.
// Block: 256 thr (8 warps), tile M=128 x N=64, K-chunk 64, cp.async double-buffer.
// Warp grid 4(m) x 2(n): warp tile 32x32 = 2(m16) x 4(n8) mma tiles.
__global__ void __launch_bounds__(256) xproj_hmma_kernel(
    const float* __restrict__ b_ih, const float* __restrict__ b_hh) {
    __shared__ __align__(16) char sm[49152];  // A: 2x16KB @0, B: 2x8KB @32768
    const uint32_t smA = smem_u32(sm);
    const uint32_t smB = smA + 32768;
    int tid = threadIdx.x, wid = tid >> 5, lane = tid & 31;
    int gbase = blockIdx.x * 64;
    int warp_m = wid & 3, warp_n = wid >> 2;
    int M0 = warp_m * 32, N0 = warp_n * 32;

    float acc[2][4][4];
#pragma unroll
    for (int mi = 0; mi < 2; mi++)
#pragma unroll
        for (int ni = 0; ni < 4; ni++)
#pragma unroll
            for (int q = 0; q < 4; q++) acc[mi][ni][q] = 0.f;

    // per-thread global src indices for the loader
    //   A: 4 tiles/thread: idx = tid + q*256: m = idx>>3, seg = idx&7
    //   B: 2 tiles/thread: idx = tid + q*256: n = idx>>3, seg = idx&7
    auto issue_stage = [&](int c, int buf) {
        int kc = c * 64;
#pragma unroll
        for (int q = 0; q < 4; q++) {
            int idx = tid + q * 256;
            int m = idx >> 3, seg = idx & 7;
            const __half* src = g_seq_h + (size_t)m * 2048 + kc + seg * 8;
            uint32_t dst = smA + buf * 16384 + SWZ(m * 128 + seg * 16);
            CP_ASYNC16(dst, src);
        }
#pragma unroll
        for (int q = 0; q < 2; q++) {
            int idx = tid + q * 256;
            int n = idx >> 3, seg = idx & 7;
            const __half* src = g_Wih_h + (size_t)(gbase + n) * 2048 + kc + seg * 8;
            uint32_t dst = smB + buf * 8192 + SWZ(n * 128 + seg * 16);
            CP_ASYNC16(dst, src);
        }
    };

    issue_stage(0, 0);
    CP_COMMIT();

    for (int c = 0; c < 32; c++) {
        int buf = c & 1;
        if (c + 1 < 32) issue_stage(c + 1, buf ^ 1);
        CP_COMMIT();
        asm volatile("cp.async.wait_group 1;" ::: "memory");
        __syncthreads();

        uint32_t baseA = smA + buf * 16384;
        uint32_t baseB = smB + buf * 8192;
#pragma unroll
        for (int ks = 0; ks < 4; ks++) {
            uint32_t a[2][4];
#pragma unroll
            for (int mi = 0; mi < 2; mi++) {
                int r = M0 + mi * 16 + (lane & 7) + ((lane >> 3) & 1) * 8;
                int kb = ks * 2 + (lane >> 4);
                uint32_t addr = baseA + SWZ(r * 128 + kb * 16);
                asm volatile(
                    "ldmatrix.sync.aligned.m8n8.x4.shared.b16 {%0,%1,%2,%3}, [%4];"
                    : "=r"(a[mi][0]), "=r"(a[mi][1]), "=r"(a[mi][2]), "=r"(a[mi][3])
                    : "r"(addr));
            }
            uint32_t b[4][2];
#pragma unroll
            for (int ni = 0; ni < 4; ni++) {
                int l2 = lane & 15;
                int n = N0 + ni * 8 + (l2 & 7);
                int kb = ks * 2 + (l2 >> 3);
                uint32_t addr = baseB + SWZ(n * 128 + kb * 16);
                asm volatile(
                    "ldmatrix.sync.aligned.m8n8.x2.shared.b16 {%0,%1}, [%2];"
                    : "=r"(b[ni][0]), "=r"(b[ni][1]) : "r"(addr));
            }
#pragma unroll
            for (int mi = 0; mi < 2; mi++)
#pragma unroll
                for (int ni = 0; ni < 4; ni++) {
                    asm volatile(
                        "mma.sync.aligned.m16n8k16.row.col.f32.f16.f16.f32 "
                        "{%0,%1,%2,%3}, {%4,%5,%6,%7}, {%8,%9}, {%0,%1,%2,%3};"
                        : "+f"(acc[mi][ni][0]), "+f"(acc[mi][ni][1]),
                          "+f"(acc[mi][ni][2]), "+f"(acc[mi][ni][3])
                        : "r"(a[mi][0]), "r"(a[mi][1]), "r"(a[mi][2]), "r"(a[mi][3]),
                          "r"(b[ni][0]), "r"(b[ni][1]));
                }
        }
        __syncthreads();
    }

    // epilogue: c0,c1 -> row r, cols g,g+1 ; c2,c3 -> row r+8
#pragma unroll
    for (int mi = 0; mi < 2; mi++)
#pragma unroll
        for (int ni = 0; ni < 4; ni++) {
            int g = gbase + N0 + ni * 8 + (lane & 3) * 2;
            float bias0 = b_ih[g] + b_hh[g];
            float bias1 = b_ih[g + 1] + b_hh[g + 1];
#pragma unroll
            for (int half_ = 0; half_ < 2; half_++) {
                int m = M0 + mi * 16 + (lane >> 2) + half_ * 8;
                int tt = m & 31, bb = m >> 5;
                float* outp = g_xproj + (size_t)tt * BB * GATES + (size_t)bb * GATES + g;
                float2 v;
                v.x = acc[mi][ni][half_ * 2 + 0] + bias0;
                v.y = acc[mi][ni][half_ * 2 + 1] + bias1;
                *(float2*)outp = v;
            }
        }
}

// ---------- 5) init h,c ----------
__global__ void init_hc_kernel() {
    int idx = blockIdx.x * 256 + threadIdx.x;  // < 32768
    if (idx < BB * LSTM_H) g_h2[0][idx] = 0.f;
    else g_c[idx - BB * LSTM_H] = 0.f;
}

// ---------- 6) fused LSTM step with cp.async weight pipeline -----------------
// Warp = one hidden index j: all 4 gate rows x 4 batches. Weight rows streamed
// through a 4-stage per-warp smem ring via cp.async (deep MLP, no reg cost).
// Block = 4 warps, grid = 1024.
__global__ void __launch_bounds__(128) lstm_step_kernel(int t) {
    __shared__ __align__(16) char wsm[4 * 4 * 4 * 512];  // [warp][stage][gate][512B]
    const float* __restrict__ hin = g_h2[t & 1];
    float* __restrict__ hout = g_h2[(t + 1) & 1];
    int warp = threadIdx.x >> 5, lane = threadIdx.x & 31;
    int j = blockIdx.x * 4 + warp;
    uint32_t wbase = smem_u32(wsm) + warp * 8192 + lane * 16;

    const __half* wrow[4];
#pragma unroll
    for (int g = 0; g < 4; g++)
        wrow[g] = g_Whh_h + (size_t)(g * LSTM_H + j) * LSTM_H + lane * 8;

    // prologue: stage chunks 0..3
#pragma unroll
    for (int c = 0; c < 4; c++) {
#pragma unroll
        for (int g = 0; g < 4; g++)
            CP_ASYNC16(wbase + c * 2048 + g * 512, wrow[g] + c * 256);
        CP_COMMIT();
    }

    unsigned long long acc[4][4];  // [gate][batch] packed f32x2
#pragma unroll
    for (int g = 0; g < 4; g++)
#pragma unroll
        for (int b = 0; b < 4; b++) acc[g][b] = 0ull;

#pragma unroll 1
    for (int kk = 0; kk < 16; kk++) {
        asm volatile("cp.async.wait_group 3;" ::: "memory");
        int stage = kk & 3;
        int k = kk * 256 + lane * 8;

        // read this chunk's 4 weight fragments from smem
        uint4 wraw[4];
#pragma unroll
        for (int g = 0; g < 4; g++) {
            uint32_t a = wbase + stage * 2048 + g * 512;
            asm volatile("ld.shared.v4.u32 {%0,%1,%2,%3}, [%4];"
                         : "=r"(wraw[g].x), "=r"(wraw[g].y),
                           "=r"(wraw[g].z), "=r"(wraw[g].w)
                         : "r"(a));
        }
        unsigned long long wp[4][4];
#pragma unroll
        for (int g = 0; g < 4; g++) {
            const __half2* wh = (const __half2*)&wraw[g];
#pragma unroll
            for (int p = 0; p < 4; p++) {
                float2 wf = __half22float2(wh[p]);
                wp[g][p] = pack2(wf.x, wf.y);
            }
        }
#pragma unroll
        for (int b = 0; b < 4; b++) {
            const ulonglong2* hp = (const ulonglong2*)(hin + b * LSTM_H + k);
            ulonglong2 h01 = hp[0];
            ulonglong2 h23 = hp[1];
#pragma unroll
            for (int g = 0; g < 4; g++) {
                ffma2(acc[g][b], wp[g][0], h01.x);
                ffma2(acc[g][b], wp[g][1], h01.y);
                ffma2(acc[g][b], wp[g][2], h23.x);
                ffma2(acc[g][b], wp[g][3], h23.y);
            }
        }

        // refill this stage with chunk kk+4 (FMAs above consumed the LDS data,
        // so the smem reads completed before these writes can land)
        if (kk < 12) {
            int c = kk + 4;
#pragma unroll
            for (int g = 0; g < 4; g++)
                CP_ASYNC16(wbase + stage * 2048 + g * 512, wrow[g] + c * 256);
        }
        CP_COMMIT();  // empty group in the tail keeps wait_group counts aligned
    }

    // fold f32x2 -> scalar, butterfly so every lane holds all 16 totals
    float v[4][4];
#pragma unroll
    for (int g = 0; g < 4; g++)
#pragma unroll
        for (int b = 0; b < 4; b++) {
            float2 f = unpack2(acc[g][b]);
            float s = f.x + f.y;
#pragma unroll
            for (int off = 16; off; off >>= 1)
                s += __shfl_xor_sync(0xffffffffu, s, off);
            v[g][b] = s;
        }

    if (lane < 4) {
        int b = lane;
        const float* xp = g_xproj + (size_t)t * BB * GATES + (size_t)b * GATES;
        float gi = v[0][b] + xp[j];
        float gf = v[1][b] + xp[LSTM_H + j];
        float gg = v[2][b] + xp[2 * LSTM_H + j];
        float go = v[3][b] + xp[3 * LSTM_H + j];
        float c = g_c[b * LSTM_H + j];
        float si = 1.f / (1.f + expf(-gi));
        float sf = 1.f / (1.f + expf(-gf));
        float so = 1.f / (1.f + expf(-go));
        c = sf * c + si * tanhf(gg);
        g_c[b * LSTM_H + j] = c;
        hout[b * LSTM_H + j] = so * tanhf(c);
    }
}

// ---------- 7) final FC ----------
__global__ void final_fc_kernel(const float* __restrict__ fcW,
                                const float* __restrict__ fcb,
                                float* __restrict__ out) {
    int tid = threadIdx.x;  // 128
    int b = tid >> 5, n = tid & 31;
    const float* hp = g_h2[0] + (size_t)b * LSTM_H + n * 128;  // t=31 writes buf 0
    float s = fcb[0];
#pragma unroll 8
    for (int l = 0; l < 128; l++) s += hp[l] * fcW[l];
    out[tid] = s;
}

extern "C" void kernel_launch(void* const* d_in, const int* in_sizes, int n_in,
                              void* d_out, int out_size) {
    const float* x    = (const float*)d_in[0];
    const int*   ei   = (const int*)d_in[1];
    const float* ln_g = (const float*)d_in[2];
    const float* ln_b = (const float*)d_in[3];
    const float* W1   = (const float*)d_in[4];
    const float* b1   = (const float*)d_in[5];
    const float* W2   = (const float*)d_in[6];
    const float* b2   = (const float*)d_in[7];
    const float* W_ih = (const float*)d_in[8];
    const float* b_ih = (const float*)d_in[9];
    const float* W_hh = (const float*)d_in[10];
    const float* b_hh = (const float*)d_in[11];
    const float* fc_W = (const float*)d_in[12];
    const float* fc_b = (const float*)d_in[13];
    float* out = (float*)d_out;

    build_adj_kernel<<<1, 256>>>(ei);
    gcn_kernel<<<128, 256>>>(x, ln_g, ln_b, W1, b1, W2, b2);
    convert_whh_kernel<<<65536, 256>>>(W_hh);   // 67M elems
    convert_wih_kernel<<<32768, 256>>>(W_ih);   // 33.5M elems
    xproj_hmma_kernel<<<256, 256>>>(b_ih, b_hh);
    init_hc_kernel<<<128, 256>>>();
    for (int t = 0; t < TT; t++) {
        lstm_step_kernel<<<1024, 128>>>(t);
    }
    final_fc_kernel<<<1, 128>>>(fc_W, fc_b, out);
}

// round 6
// speedup vs baseline: 2.6957x; 1.2879x over previous
#include <cuda_runtime.h>
#include <cuda_fp16.h>
#include <cstdint>

// Problem constants
#define BB 4
#define TT 32
#define NN 32
#define FF 16
#define GH 64
#define LSTM_IN 2048     // NN*GH
#define LSTM_H 4096
#define GATES 16384      // 4*LSTM_H
#define E_EDGES 256

// Scratch (device globals; no dynamic allocation allowed)
__device__ float g_A[NN * NN];
__device__ __align__(16) __half g_seq_h[BB * TT * LSTM_IN];       // 512 KB fp16
__device__ float g_xproj[TT * BB * GATES];                        // 8 MB
__device__ __align__(16) float g_h2[2][BB * LSTM_H];              // double-buffered hidden
__device__ float g_c[BB * LSTM_H];
__device__ __align__(16) __half g_Whh_h[(size_t)GATES * LSTM_H];  // 128 MiB fp16
__device__ __align__(16) __half g_Wih_h[(size_t)GATES * LSTM_IN]; // 64 MiB fp16

__device__ __forceinline__ uint32_t smem_u32(const void* p) {
    return (uint32_t)__cvta_generic_to_shared(p);
}
#define CP_ASYNC16(dst_u32, src_ptr) \
    asm volatile("cp.async.cg.shared.global [%0], [%1], 16;" :: "r"(dst_u32), "l"(src_ptr))
#define CP_COMMIT() asm volatile("cp.async.commit_group;" ::: "memory")
#define SWZ(x) ((x) ^ (((x) >> 3) & 0x70))

// ---------- 1) adjacency build (handles int32 or int64 edge_index) ----------
__global__ void build_adj_kernel(const int* __restrict__ ei32) {
    __shared__ int is32flag;
    __shared__ int deg[NN];
    __shared__ float dinv[NN];
    __shared__ float As[NN * NN];
    int tid = threadIdx.x;
    if (tid == 0) is32flag = 0;
    for (int i = tid; i < NN; i += blockDim.x) deg[i] = 1;  // self loop
    for (int i = tid; i < NN * NN; i += blockDim.x) As[i] = 0.f;
    __syncthreads();
    int any = 0;
    for (int w = tid * 2 + 1; w < 512; w += blockDim.x * 2) any |= ei32[w];
    if (any) atomicOr(&is32flag, 1);
    __syncthreads();
    const int is32 = is32flag;
    for (int e = tid; e < E_EDGES; e += blockDim.x) {
        int dst = is32 ? ei32[E_EDGES + e] : ei32[2 * (E_EDGES + e)];
        atomicAdd(&deg[dst], 1);
    }
    __syncthreads();
    for (int i = tid; i < NN; i += blockDim.x) dinv[i] = rsqrtf((float)deg[i]);
    __syncthreads();
    for (int e = tid; e < E_EDGES; e += blockDim.x) {
        int src = is32 ? ei32[e] : ei32[2 * e];
        int dst = is32 ? ei32[E_EDGES + e] : ei32[2 * (E_EDGES + e)];
        atomicAdd(&As[dst * NN + src], dinv[src] * dinv[dst]);
    }
    for (int n = tid; n < NN; n += blockDim.x)
        atomicAdd(&As[n * NN + n], dinv[n] * dinv[n]);
    __syncthreads();
    for (int i = tid; i < NN * NN; i += blockDim.x) g_A[i] = As[i];
}

// ---------- 2) LayerNorm + GCN x2 -> seq (fp16) ----------
__global__ void __launch_bounds__(256) gcn_kernel(
    const float* __restrict__ x, const float* __restrict__ ln_g,
    const float* __restrict__ ln_b, const float* __restrict__ W1,
    const float* __restrict__ b1, const float* __restrict__ W2,
    const float* __restrict__ b2) {
    __shared__ float xln[NN * FF];
    __shared__ float bufA[NN * GH];
    __shared__ float bufB[NN * GH];
    __shared__ float As[NN * NN];
    int tid = threadIdx.x;
    int bt = blockIdx.x;  // b*TT + t
    const float* xp = x + (size_t)bt * NN * FF;

    for (int i = tid; i < NN * NN; i += 256) As[i] = g_A[i];
    if (tid < NN) {
        float v[FF];
        float mu = 0.f;
#pragma unroll
        for (int f = 0; f < FF; f++) { v[f] = xp[tid * FF + f]; mu += v[f]; }
        mu *= (1.f / FF);
        float var = 0.f;
#pragma unroll
        for (int f = 0; f < FF; f++) { float d = v[f] - mu; var += d * d; }
        var *= (1.f / FF);
        float r = rsqrtf(var + 1e-5f);
#pragma unroll
        for (int f = 0; f < FF; f++)
            xln[tid * FF + f] = (v[f] - mu) * r * ln_g[f] + ln_b[f];
    }
    __syncthreads();
    for (int o = tid; o < NN * GH; o += 256) {
        int n = o >> 6, g = o & 63;
        float s = 0.f;
#pragma unroll
        for (int f = 0; f < FF; f++) s += xln[n * FF + f] * W1[f * GH + g];
        bufA[o] = s;
    }
    __syncthreads();
    for (int o = tid; o < NN * GH; o += 256) {
        int n = o >> 6, g = o & 63;
        float s = b1[g];
#pragma unroll 8
        for (int sn = 0; sn < NN; sn++) s += As[n * NN + sn] * bufA[sn * GH + g];
        bufB[o] = s;
    }
    __syncthreads();
    for (int o = tid; o < NN * GH; o += 256) {
        int n = o >> 6, g = o & 63;
        float s = 0.f;
#pragma unroll 8
        for (int f = 0; f < GH; f++) s += bufB[n * GH + f] * W2[f * GH + g];
        bufA[o] = s;
    }
    __syncthreads();
    for (int o = tid; o < NN * GH; o += 256) {
        int n = o >> 6, g = o & 63;
        float s = b2[g];
#pragma unroll 8
        for (int sn = 0; sn < NN; sn++) s += As[n * NN + sn] * bufA[sn * GH + g];
        g_seq_h[(size_t)bt * LSTM_IN + o] = __float2half_rn(s);
    }
}

// ---------- 3) converts ----------
__global__ void __launch_bounds__(256) convert_whh_kernel(const float* __restrict__ Whh) {
    size_t i = ((size_t)blockIdx.x * 256 + threadIdx.x) * 4;
    float4 v = *(const float4*)(Whh + i);
    __half2* out = (__half2*)(g_Whh_h + i);
    out[0] = __floats2half2_rn(v.x, v.y);
    out[1] = __floats2half2_rn(v.z, v.w);
}
__global__ void __launch_bounds__(256) convert_wih_kernel(const float* __restrict__ Wih) {
    size_t i = ((size_t)blockIdx.x * 256 + threadIdx.x) * 4;
    float4 v = *(const float4*)(Wih + i);
    __half2* out = (__half2*)(g_Wih_h + i);
    out[0] = __floats2half2_rn(v.x, v.y);
    out[1] = __floats2half2_rn(v.z, v.w);
}

// ---------- 4) x_proj GEMM on tensor cores (HMMA) -----------------------------
__global__ void __launch_bounds__(256) xproj_hmma_kernel(
    const float* __restrict__ b_ih, const float* __restrict__ b_hh) {
    __shared__ __align__(16) char sm[49152];  // A: 2x16KB @0, B: 2x8KB @32768
    const uint32_t smA = smem_u32(sm);
    const uint32_t smB = smA + 32768;
    int tid = threadIdx.x, wid = tid >> 5, lane = tid & 31;
    int gbase = blockIdx.x * 64;
    int warp_m = wid & 3, warp_n = wid >> 2;
    int M0 = warp_m * 32, N0 = warp_n * 32;

    float acc[2][4][4];
#pragma unroll
    for (int mi = 0; mi < 2; mi++)
#pragma unroll
        for (int ni = 0; ni < 4; ni++)
#pragma unroll
            for (int q = 0; q < 4; q++) acc[mi][ni][q] = 0.f;

    auto issue_stage = [&](int c, int buf) {
        int kc = c * 64;
#pragma unroll
        for (int q = 0; q < 4; q++) {
            int idx = tid + q * 256;
            int m = idx >> 3, seg = idx & 7;
            const __half* src = g_seq_h + (size_t)m * 2048 + kc + seg * 8;
            uint32_t dst = smA + buf * 16384 + SWZ(m * 128 + seg * 16);
            CP_ASYNC16(dst, src);
        }
#pragma unroll
        for (int q = 0; q < 2; q++) {
            int idx = tid + q * 256;
            int n = idx >> 3, seg = idx & 7;
            const __half* src = g_Wih_h + (size_t)(gbase + n) * 2048 + kc + seg * 8;
            uint32_t dst = smB + buf * 8192 + SWZ(n * 128 + seg * 16);
            CP_ASYNC16(dst, src);
        }
    };

    issue_stage(0, 0);
    CP_COMMIT();

    for (int c = 0; c < 32; c++) {
        int buf = c & 1;
        if (c + 1 < 32) issue_stage(c + 1, buf ^ 1);
        CP_COMMIT();
        asm volatile("cp.async.wait_group 1;" ::: "memory");
        __syncthreads();

        uint32_t baseA = smA + buf * 16384;
        uint32_t baseB = smB + buf * 8192;
#pragma unroll
        for (int ks = 0; ks < 4; ks++) {
            uint32_t a[2][4];
#pragma unroll
            for (int mi = 0; mi < 2; mi++) {
                int r = M0 + mi * 16 + (lane & 7) + ((lane >> 3) & 1) * 8;
                int kb = ks * 2 + (lane >> 4);
                uint32_t addr = baseA + SWZ(r * 128 + kb * 16);
                asm volatile(
                    "ldmatrix.sync.aligned.m8n8.x4.shared.b16 {%0,%1,%2,%3}, [%4];"
                    : "=r"(a[mi][0]), "=r"(a[mi][1]), "=r"(a[mi][2]), "=r"(a[mi][3])
                    : "r"(addr));
            }
            uint32_t b[4][2];
#pragma unroll
            for (int ni = 0; ni < 4; ni++) {
                int l2 = lane & 15;
                int n = N0 + ni * 8 + (l2 & 7);
                int kb = ks * 2 + (l2 >> 3);
                uint32_t addr = baseB + SWZ(n * 128 + kb * 16);
                asm volatile(
                    "ldmatrix.sync.aligned.m8n8.x2.shared.b16 {%0,%1}, [%2];"
                    : "=r"(b[ni][0]), "=r"(b[ni][1]) : "r"(addr));
            }
#pragma unroll
            for (int mi = 0; mi < 2; mi++)
#pragma unroll
                for (int ni = 0; ni < 4; ni++) {
                    asm volatile(
                        "mma.sync.aligned.m16n8k16.row.col.f32.f16.f16.f32 "
                        "{%0,%1,%2,%3}, {%4,%5,%6,%7}, {%8,%9}, {%0,%1,%2,%3};"
                        : "+f"(acc[mi][ni][0]), "+f"(acc[mi][ni][1]),
                          "+f"(acc[mi][ni][2]), "+f"(acc[mi][ni][3])
                        : "r"(a[mi][0]), "r"(a[mi][1]), "r"(a[mi][2]), "r"(a[mi][3]),
                          "r"(b[ni][0]), "r"(b[ni][1]));
                }
        }
        __syncthreads();
    }

#pragma unroll
    for (int mi = 0; mi < 2; mi++)
#pragma unroll
        for (int ni = 0; ni < 4; ni++) {
            int g = gbase + N0 + ni * 8 + (lane & 3) * 2;
            float bias0 = b_ih[g] + b_hh[g];
            float bias1 = b_ih[g + 1] + b_hh[g + 1];
#pragma unroll
            for (int half_ = 0; half_ < 2; half_++) {
                int m = M0 + mi * 16 + (lane >> 2) + half_ * 8;
                int tt = m & 31, bb = m >> 5;
                float* outp = g_xproj + (size_t)tt * BB * GATES + (size_t)bb * GATES + g;
                float2 v;
                v.x = acc[mi][ni][half_ * 2 + 0] + bias0;
                v.y = acc[mi][ni][half_ * 2 + 1] + bias1;
                *(float2*)outp = v;
            }
        }
}

// ---------- 5) init h,c ----------
__global__ void init_hc_kernel() {
    int idx = blockIdx.x * 256 + threadIdx.x;  // < 32768
    if (idx < BB * LSTM_H) g_h2[0][idx] = 0.f;
    else g_c[idx - BB * LSTM_H] = 0.f;
}

// ---------- 6) fused LSTM step: HMMA streaming GEMM + cell update ------------
// Block (128 thr, 4 warps) owns 8 hidden indices j0..j0+7 => 32 W_hh rows
// (warp = gate, n8 tile = 8 j's). W streamed via 4-stage cp.async ring (8KB
// stages, K-chunk 128). A = 4 h rows (fp32->fp16 in-register), zero-padded to
// m16. Grid = 512 blocks.
__global__ void __launch_bounds__(128) lstm_step_mma_kernel(int t) {
    // [stage][subchunk(64h)][row 32][64 halves], swizzled 128B rows = 32 KB
    __shared__ __align__(16) __half Bsm[4 * 2 * 32 * 64];
    __shared__ float sgate[4][4][8];  // [gate][batch][jj]
    const uint32_t smB = smem_u32(Bsm);
    const float* __restrict__ hin = g_h2[t & 1];
    float* __restrict__ hout = g_h2[(t + 1) & 1];
    int tid = threadIdx.x;
    int gate = tid >> 5, lane = tid & 31;
    int j0 = blockIdx.x * 8;

    auto load_stage = [&](int s, int cc) {
        int kc = cc * 128;
#pragma unroll
        for (int q = 0; q < 4; q++) {
            int idx = tid + q * 128;
            int r = idx >> 4, seg = idx & 15;
            const __half* src = g_Whh_h +
                (size_t)((r >> 3) * LSTM_H + j0 + (r & 7)) * LSTM_H + kc + seg * 8;
            uint32_t dst = smB + s * 8192 + (seg >> 3) * 4096 + SWZ(r * 128 + (seg & 7) * 16);
            CP_ASYNC16(dst, src);
        }
    };

    load_stage(0, 0); CP_COMMIT();
    load_stage(1, 1); CP_COMMIT();
    load_stage(2, 2); CP_COMMIT();

    float c0 = 0.f, c1 = 0.f, c2 = 0.f, c3 = 0.f;
    const uint32_t zero = 0;
    const int l2 = lane & 15;
    const bool aval = lane < 16;
    const float* hrow = hin + (lane >> 2) * LSTM_H + (lane & 3) * 2;  // lanes<16

    for (int cc = 0; cc < 32; cc++) {
        asm volatile("cp.async.wait_group 2;" ::: "memory");
        __syncthreads();
        if (cc + 3 < 32) load_stage((cc + 3) & 3, cc + 3);
        CP_COMMIT();
        uint32_t stageBase = smB + (cc & 3) * 8192;
#pragma unroll
        for (int i = 0; i < 8; i++) {
            uint32_t a0 = 0, a2 = 0;
            if (aval) {
                const float* hq = hrow + cc * 128 + i * 16;
                float2 hlo = *(const float2*)hq;
                float2 hhi = *(const float2*)(hq + 8);
                __half2 p0 = __floats2half2_rn(hlo.x, hlo.y);
                __half2 p1 = __floats2half2_rn(hhi.x, hhi.y);
                a0 = *(uint32_t*)&p0;
                a2 = *(uint32_t*)&p1;
            }
            uint32_t addr = stageBase + (i >> 2) * 4096 +
                SWZ((gate * 8 + (l2 & 7)) * 128 + (((i & 3) * 2) + (l2 >> 3)) * 16);
            uint32_t b0, b1;
            asm volatile("ldmatrix.sync.aligned.m8n8.x2.shared.b16 {%0,%1}, [%2];"
                         : "=r"(b0), "=r"(b1) : "r"(addr));
            asm volatile(
                "mma.sync.aligned.m16n8k16.row.col.f32.f16.f16.f32 "
                "{%0,%1,%2,%3}, {%4,%5,%6,%7}, {%8,%9}, {%0,%1,%2,%3};"
                : "+f"(c0), "+f"(c1), "+f"(c2), "+f"(c3)
                : "r"(a0), "r"(zero), "r"(a2), "r"(zero), "r"(b0), "r"(b1));
        }
    }

    // lanes 0-15: batch = lane>>2, columns jj = (lane&3)*2, +1
    if (aval) {
        int b = lane >> 2, jj = (lane & 3) * 2;
        sgate[gate][b][jj] = c0;
        sgate[gate][b][jj + 1] = c1;
    }
    __syncthreads();
    if (tid < 32) {
        int b = tid >> 3, jj = tid & 7;
        int j = j0 + jj;
        const float* xp = g_xproj + (size_t)t * BB * GATES + (size_t)b * GATES;
        float gi = sgate[0][b][jj] + xp[j];
        float gf = sgate[1][b][jj] + xp[LSTM_H + j];
        float gg = sgate[2][b][jj] + xp[2 * LSTM_H + j];
        float go = sgate[3][b][jj] + xp[3 * LSTM_H + j];
        float c = g_c[b * LSTM_H + j];
        float si = 1.f / (1.f + expf(-gi));
        float sf = 1.f / (1.f + expf(-gf));
        float so = 1.f / (1.f + expf(-go));
        c = sf * c + si * tanhf(gg);
        g_c[b * LSTM_H + j] = c;
        hout[b * LSTM_H + j] = so * tanhf(c);
    }
}

// ---------- 7) final FC ----------
__global__ void final_fc_kernel(const float* __restrict__ fcW,
                                const float* __restrict__ fcb,
                                float* __restrict__ out) {
    int tid = threadIdx.x;  // 128
    int b = tid >> 5, n = tid & 31;
    const float* hp = g_h2[0] + (size_t)b * LSTM_H + n * 128;  // t=31 writes buf 0
    float s = fcb[0];
#pragma unroll 8
    for (int l = 0; l < 128; l++) s += hp[l] * fcW[l];
    out[tid] = s;
}

extern "C" void kernel_launch(void* const* d_in, const int* in_sizes, int n_in,
                              void* d_out, int out_size) {
    const float* x    = (const float*)d_in[0];
    const int*   ei   = (const int*)d_in[1];
    const float* ln_g = (const float*)d_in[2];
    const float* ln_b = (const float*)d_in[3];
    const float* W1   = (const float*)d_in[4];
    const float* b1   = (const float*)d_in[5];
    const float* W2   = (const float*)d_in[6];
    const float* b2   = (const float*)d_in[7];
    const float* W_ih = (const float*)d_in[8];
    const float* b_ih = (const float*)d_in[9];
    const float* W_hh = (const float*)d_in[10];
    const float* b_hh = (const float*)d_in[11];
    const float* fc_W = (const float*)d_in[12];
    const float* fc_b = (const float*)d_in[13];
    float* out = (float*)d_out;

    // Order chosen so launch #4 (the one ncu captures) is xproj_hmma.
    build_adj_kernel<<<1, 256>>>(ei);
    gcn_kernel<<<128, 256>>>(x, ln_g, ln_b, W1, b1, W2, b2);
    convert_wih_kernel<<<32768, 256>>>(W_ih);
    xproj_hmma_kernel<<<256, 256>>>(b_ih, b_hh);
    convert_whh_kernel<<<65536, 256>>>(W_hh);
    init_hc_kernel<<<128, 256>>>();
    for (int t = 0; t < TT; t++) {
        lstm_step_mma_kernel<<<512, 128>>>(t);
    }
    final_fc_kernel<<<1, 128>>>(fc_W, fc_b, out);
}